// round 1
// baseline (speedup 1.0000x reference)
#include <cuda_runtime.h>
#include <math.h>

// ---------------- problem constants ----------------
#define BATCH   2
#define SEQ     2048
#define NTOK    (BATCH*SEQ)      // 4096
#define DMODEL  512
#define NHEAD   8
#define DHEAD   64
#define NLAYER  4
#define FFDIM   2048
#define SLOTS   32768
#define TOPK    8
#define VSIZE   32000

// ---------------- scratch (device globals; allocation-free rule) ----------------
__device__ float g_x  [NTOK*DMODEL];
__device__ float g_q  [NTOK*DMODEL];
__device__ float g_k  [NTOK*DMODEL];
__device__ float g_v  [NTOK*DMODEL];
__device__ float g_ao [NTOK*DMODEL];
__device__ float g_mq [NTOK*DMODEL];
__device__ float g_rd [NTOK*DMODEL];
__device__ float g_ffh[NTOK*FFDIM];
__device__ float g_big[(long long)NTOK*SLOTS];   // 512MB: attn scores (268MB) & mem scores (512MB), disjoint lifetimes

// ---------------- helpers ----------------
__device__ __forceinline__ float gelu_tanh(float x) {
    float x3 = x*x*x;
    return 0.5f*x*(1.f + tanhf(0.7978845608028654f*(x + 0.044715f*x3)));
}

// ---------------- generic tiled GEMM ----------------
// C[r,c] = alpha * sum_k A[r,k]*B(k,c)  (+bias[c]) (+res[r,c]) (opt gelu)
// TB=false: B is [K,N] (ldb=N typ).  TB=true: B is [N,K] (ldb=K typ), B(k,c)=B[c*ldb+k]
// Batched via blockIdx.z: off = (z/zdiv)*s1 + (z%zdiv)*s2 applied to A,B,C(,res).
template<int BM,int BN,int BK,int TM,int TN,bool TB,bool GELU>
__global__ __launch_bounds__((BM/TM)*(BN/TN))
void gemm_kernel(const float* __restrict__ A, int lda,
                 const float* __restrict__ B, int ldb,
                 const float* __restrict__ bias,
                 const float* __restrict__ res,
                 float* __restrict__ C, int ldc,
                 int K, float alpha,
                 long long sA1, long long sA2,
                 long long sB1, long long sB2,
                 long long sC1, long long sC2, int zdiv)
{
    constexpr int THREADS = (BM/TM)*(BN/TN);
    const int z  = blockIdx.z;
    const int z1 = z / zdiv;
    const int z2 = z - z1*zdiv;
    A += z1*sA1 + z2*sA2;
    B += z1*sB1 + z2*sB2;
    const long long coff = z1*sC1 + z2*sC2;
    C += coff;
    if (res) res += coff;

    __shared__ float As[BK][BM+4];
    __shared__ float Bs[BK][BN+4];

    const int tid = threadIdx.x;
    const int tx  = tid % (BN/TN);
    const int ty  = tid / (BN/TN);
    const long long row0 = (long long)blockIdx.y * BM;
    const long long col0 = (long long)blockIdx.x * BN;

    float acc[TM][TN];
#pragma unroll
    for (int i = 0; i < TM; i++)
#pragma unroll
        for (int j = 0; j < TN; j++) acc[i][j] = 0.f;

    for (int k0 = 0; k0 < K; k0 += BK) {
        // A tile -> As[kk][i] (transposed store)
#pragma unroll
        for (int u = 0; u < (BM*BK)/THREADS; u++) {
            int t  = tid + u*THREADS;
            int i  = t / BK;
            int kk = t - i*BK;
            As[kk][i] = A[(row0 + i)*lda + (k0 + kk)];
        }
        // B tile -> Bs[kk][j]
        if (!TB) {
#pragma unroll
            for (int u = 0; u < (BK*BN)/THREADS; u++) {
                int t  = tid + u*THREADS;
                int kk = t / BN;
                int j  = t - kk*BN;
                Bs[kk][j] = B[(long long)(k0 + kk)*ldb + (col0 + j)];
            }
        } else {
#pragma unroll
            for (int u = 0; u < (BK*BN)/THREADS; u++) {
                int t  = tid + u*THREADS;
                int j  = t / BK;
                int kk = t - j*BK;
                Bs[kk][j] = B[(col0 + j)*ldb + (k0 + kk)];
            }
        }
        __syncthreads();
#pragma unroll
        for (int kk = 0; kk < BK; kk++) {
            float a[TM], b[TN];
#pragma unroll
            for (int i = 0; i < TM; i++) a[i] = As[kk][ty*TM + i];
#pragma unroll
            for (int j = 0; j < TN; j++) b[j] = Bs[kk][tx*TN + j];
#pragma unroll
            for (int i = 0; i < TM; i++)
#pragma unroll
                for (int j = 0; j < TN; j++) acc[i][j] += a[i]*b[j];
        }
        __syncthreads();
    }

    // epilogue
#pragma unroll
    for (int i = 0; i < TM; i++) {
        long long r = row0 + ty*TM + i;
#pragma unroll
        for (int j = 0; j < TN; j++) {
            long long c = col0 + tx*TN + j;
            float vv = acc[i][j]*alpha;
            if (bias) vv += __ldg(bias + c);
            if (res)  vv += res[r*ldc + c];
            if (GELU) vv = gelu_tanh(vv);
            C[r*ldc + c] = vv;
        }
    }
}

// ---------------- small kernels ----------------
__global__ void embed_kernel(const int* __restrict__ ids,
                             const float* __restrict__ tok,
                             const float* __restrict__ pos,
                             float* __restrict__ x)
{
    int tkn = blockIdx.x;
    int t   = tkn & (SEQ-1);
    int id  = ids[tkn];
    const float* te = tok + (long long)id*DMODEL;
    const float* pe = pos + (long long)t*DMODEL;
    float* xp = x + (long long)tkn*DMODEL;
    for (int d = threadIdx.x; d < DMODEL; d += blockDim.x)
        xp[d] = te[d] + pe[d];
}

__global__ void softmax_rows_kernel(float* __restrict__ data)   // rows of SEQ(=2048)
{
    const int cols = SEQ;
    float* p = data + (long long)blockIdx.x * cols;
    const int tid = threadIdx.x;
    __shared__ float red[256];

    float m = -3.4e38f;
    for (int j = tid; j < cols; j += 256) m = fmaxf(m, p[j]);
    red[tid] = m; __syncthreads();
    for (int s = 128; s > 0; s >>= 1) { if (tid < s) red[tid] = fmaxf(red[tid], red[tid+s]); __syncthreads(); }
    float bm = red[0]; __syncthreads();

    float sum = 0.f;
    for (int j = tid; j < cols; j += 256) { float e = __expf(p[j]-bm); p[j] = e; sum += e; }
    red[tid] = sum; __syncthreads();
    for (int s = 128; s > 0; s >>= 1) { if (tid < s) red[tid] += red[tid+s]; __syncthreads(); }
    float inv = 1.f/red[0];
    for (int j = tid; j < cols; j += 256) p[j] *= inv;
}

__global__ void rmsnorm_kernel(float* __restrict__ x, const float* __restrict__ w)
{
    float* p = x + (long long)blockIdx.x * DMODEL;
    const int tid = threadIdx.x;       // 256 threads, 2 elems each
    float a = p[tid], b = p[tid+256];
    __shared__ float red[256];
    red[tid] = a*a + b*b; __syncthreads();
    for (int s = 128; s > 0; s >>= 1) { if (tid < s) red[tid] += red[tid+s]; __syncthreads(); }
    float scale = rsqrtf(red[0]*(1.f/DMODEL) + 1e-8f);
    p[tid]     = a*scale*w[tid];
    p[tid+256] = b*scale*w[tid+256];
}

// per-token: top-8 of 32768 scores -> softmax -> weighted gather of mem_V -> g_rd
__device__ __forceinline__ bool tk_better(float av, int ai, float bv, int bi) {
    return (av > bv) || (av == bv && ai < bi);
}
__global__ void topk_read_kernel(const float* __restrict__ scores,
                                 const float* __restrict__ memV,
                                 float* __restrict__ out)
{
    const int t = blockIdx.x;
    const float* row = scores + (long long)t * SLOTS;
    const int tid = threadIdx.x;

    float v[TOPK]; int ix[TOPK];
#pragma unroll
    for (int i = 0; i < TOPK; i++) { v[i] = -3.4e38f; ix[i] = 1<<30; }

    for (int j = tid; j < SLOTS; j += 256) {
        float s = row[j];
        if (tk_better(s, j, v[TOPK-1], ix[TOPK-1])) {
            v[TOPK-1] = s; ix[TOPK-1] = j;
#pragma unroll
            for (int p = TOPK-1; p > 0; p--) {
                if (tk_better(v[p], ix[p], v[p-1], ix[p-1])) {
                    float tv = v[p]; v[p] = v[p-1]; v[p-1] = tv;
                    int   ti = ix[p]; ix[p] = ix[p-1]; ix[p-1] = ti;
                }
            }
        }
    }

    __shared__ float sv[256][TOPK];
    __shared__ int   si[256][TOPK];
#pragma unroll
    for (int i = 0; i < TOPK; i++) { sv[tid][i] = v[i]; si[tid][i] = ix[i]; }
    __syncthreads();

    for (int s = 128; s > 0; s >>= 1) {
        if (tid < s) {
            float* mv = sv[tid]; int* mi = si[tid];
#pragma unroll
            for (int i = 0; i < TOPK; i++) {
                float cv = sv[tid+s][i]; int ci = si[tid+s][i];
                if (tk_better(cv, ci, mv[TOPK-1], mi[TOPK-1])) {
                    mv[TOPK-1] = cv; mi[TOPK-1] = ci;
#pragma unroll
                    for (int p = TOPK-1; p > 0; p--) {
                        if (tk_better(mv[p], mi[p], mv[p-1], mi[p-1])) {
                            float tv = mv[p]; mv[p] = mv[p-1]; mv[p-1] = tv;
                            int   ti = mi[p]; mi[p] = mi[p-1]; mi[p-1] = ti;
                        }
                    }
                }
            }
        }
        __syncthreads();
    }

    __shared__ float w[TOPK];
    __shared__ int   gidx[TOPK];
    if (tid == 0) {
        float m = sv[0][0];            // sorted descending -> max
        float e[TOPK], sum = 0.f;
#pragma unroll
        for (int k2 = 0; k2 < TOPK; k2++) { e[k2] = __expf(sv[0][k2]-m); sum += e[k2]; }
        float inv = 1.f/sum;
#pragma unroll
        for (int k2 = 0; k2 < TOPK; k2++) { w[k2] = e[k2]*inv; gidx[k2] = si[0][k2]; }
    }
    __syncthreads();

    for (int d = tid; d < DMODEL; d += 256) {
        float acc = 0.f;
#pragma unroll
        for (int k2 = 0; k2 < TOPK; k2++)
            acc += w[k2] * memV[(long long)gidx[k2]*DMODEL + d];
        out[(long long)t*DMODEL + d] = acc;
    }
}

// ---------------- host side ----------------
static inline void gemmNN(const float* A, int lda, const float* B, int ldb,
                          const float* bias, const float* res,
                          float* C, int ldc, int M, int N, int K, float alpha)
{
    dim3 g(N/128, M/128, 1), b(256);
    gemm_kernel<128,128,16,8,8,false,false><<<g,b>>>(A,lda,B,ldb,bias,res,C,ldc,K,alpha,0,0,0,0,0,0,1);
}
static inline void gemmNN_gelu(const float* A, int lda, const float* B, int ldb,
                               const float* bias, float* C, int ldc, int M, int N, int K)
{
    dim3 g(N/128, M/128, 1), b(256);
    gemm_kernel<128,128,16,8,8,false,true><<<g,b>>>(A,lda,B,ldb,bias,nullptr,C,ldc,K,1.f,0,0,0,0,0,0,1);
}
static inline void gemmNT(const float* A, int lda, const float* B, int ldb,
                          const float* bias, float* C, int ldc, int M, int N, int K, float alpha)
{
    dim3 g(N/128, M/128, 1), b(256);
    gemm_kernel<128,128,16,8,8,true,false><<<g,b>>>(A,lda,B,ldb,bias,nullptr,C,ldc,K,alpha,0,0,0,0,0,0,1);
}

extern "C" void kernel_launch(void* const* d_in, const int* in_sizes, int n_in,
                              void* d_out, int out_size)
{
    const int*   ids  = (const int*)  d_in[0];
    const float* tok  = (const float*)d_in[1];
    const float* pos  = (const float*)d_in[2];
    const float* wq   = (const float*)d_in[3];
    const float* wk   = (const float*)d_in[4];
    const float* wv   = (const float*)d_in[5];
    const float* wo   = (const float*)d_in[6];
    const float* bo   = (const float*)d_in[7];
    const float* n1   = (const float*)d_in[8];
    const float* fw1  = (const float*)d_in[9];
    const float* fb1  = (const float*)d_in[10];
    const float* fw2  = (const float*)d_in[11];
    const float* fb2  = (const float*)d_in[12];
    const float* n2   = (const float*)d_in[13];
    const float* memK = (const float*)d_in[14];
    const float* memV = (const float*)d_in[15];
    const float* sal  = (const float*)d_in[16];
    const float* wqm  = (const float*)d_in[17];
    const float* bqm  = (const float*)d_in[18];
    const float* wr   = (const float*)d_in[19];
    const float* br   = (const float*)d_in[20];
    const float* now  = (const float*)d_in[21];
    float* out = (float*)d_out;

    float *x,*q,*k,*v,*ao,*mq,*rd,*ffh,*big;
    cudaGetSymbolAddress((void**)&x,   g_x);
    cudaGetSymbolAddress((void**)&q,   g_q);
    cudaGetSymbolAddress((void**)&k,   g_k);
    cudaGetSymbolAddress((void**)&v,   g_v);
    cudaGetSymbolAddress((void**)&ao,  g_ao);
    cudaGetSymbolAddress((void**)&mq,  g_mq);
    cudaGetSymbolAddress((void**)&rd,  g_rd);
    cudaGetSymbolAddress((void**)&ffh, g_ffh);
    cudaGetSymbolAddress((void**)&big, g_big);

    const float inv_sqrt_dh = 0.125f;                 // 64^-0.5
    const float inv_sqrt_d  = 0.044194173824159216f;  // 512^-0.5

    embed_kernel<<<NTOK, 256>>>(ids, tok, pos, x);

    for (int l = 0; l < NLAYER; l++) {
        const float* wql = wq + (long long)l*DMODEL*DMODEL;
        const float* wkl = wk + (long long)l*DMODEL*DMODEL;
        const float* wvl = wv + (long long)l*DMODEL*DMODEL;
        const float* wol = wo + (long long)l*DMODEL*DMODEL;
        const float* bol = bo + (long long)l*DMODEL;
        const float* n1l = n1 + (long long)l*DMODEL;
        const float* f1l = fw1 + (long long)l*DMODEL*FFDIM;
        const float* b1l = fb1 + (long long)l*FFDIM;
        const float* f2l = fw2 + (long long)l*FFDIM*DMODEL;
        const float* b2l = fb2 + (long long)l*DMODEL;
        const float* n2l = n2 + (long long)l*DMODEL;

        gemmNN(x, DMODEL, wql, DMODEL, nullptr, nullptr, q, DMODEL, NTOK, DMODEL, DMODEL, 1.f);
        gemmNN(x, DMODEL, wkl, DMODEL, nullptr, nullptr, k, DMODEL, NTOK, DMODEL, DMODEL, 1.f);
        gemmNN(x, DMODEL, wvl, DMODEL, nullptr, nullptr, v, DMODEL, NTOK, DMODEL, DMODEL, 1.f);

        // scores[b,h,i,j] = 0.125 * q[b,i,h,:] . k[b,j,h,:]   (batched NT, z=(b,h))
        {
            dim3 g(SEQ/128, SEQ/128, BATCH*NHEAD), b(256);
            gemm_kernel<128,128,16,8,8,true,false><<<g,b>>>(
                q, DMODEL, k, DMODEL, nullptr, nullptr, big, SEQ,
                DHEAD, inv_sqrt_dh,
                (long long)SEQ*DMODEL, DHEAD,            // A: b, h
                (long long)SEQ*DMODEL, DHEAD,            // B: b, h
                (long long)NHEAD*SEQ*SEQ, (long long)SEQ*SEQ,  // C: b, h
                NHEAD);
        }
        softmax_rows_kernel<<<BATCH*NHEAD*SEQ, 256>>>(big);
        // ao[b,i,h,:] = attn[b,h,i,:] @ v[b,:,h,:]   (batched NN, N=64)
        {
            dim3 g(1, SEQ/64, BATCH*NHEAD), b(256);
            gemm_kernel<64,64,16,4,4,false,false><<<g,b>>>(
                big, SEQ, v, DMODEL, nullptr, nullptr, ao, DMODEL,
                SEQ, 1.f,
                (long long)NHEAD*SEQ*SEQ, (long long)SEQ*SEQ,  // A: b, h
                (long long)SEQ*DMODEL, DHEAD,                  // B: b, h
                (long long)SEQ*DMODEL, DHEAD,                  // C: b, h
                NHEAD);
        }

        gemmNN(ao, DMODEL, wol, DMODEL, bol, x, x, DMODEL, NTOK, DMODEL, DMODEL, 1.f);  // x += ao@wo+bo
        rmsnorm_kernel<<<NTOK, 256>>>(x, n1l);
        gemmNN_gelu(x, DMODEL, f1l, FFDIM, b1l, ffh, FFDIM, NTOK, FFDIM, DMODEL);       // h = gelu(x@W1+b1)
        gemmNN(ffh, FFDIM, f2l, DMODEL, b2l, x, x, DMODEL, NTOK, DMODEL, FFDIM, 1.f);   // x += h@W2+b2
        rmsnorm_kernel<<<NTOK, 256>>>(x, n2l);
    }

    // external memory read
    gemmNN(x, DMODEL, wqm, DMODEL, bqm, nullptr, mq, DMODEL, NTOK, DMODEL, DMODEL, 1.f);
    gemmNT(mq, DMODEL, memK, DMODEL, sal, big, SLOTS, NTOK, SLOTS, DMODEL, inv_sqrt_d); // +salience as bias
    topk_read_kernel<<<NTOK, 256>>>(big, memV, rd);
    gemmNN(rd, DMODEL, wr, DMODEL, br, x, x, DMODEL, NTOK, DMODEL, DMODEL, 1.f);        // x += read@w_read+b_read
    rmsnorm_kernel<<<NTOK, 256>>>(x, now);

    // tied LM head: logits = x @ tok^T
    gemmNT(x, DMODEL, tok, DMODEL, nullptr, out, VSIZE, NTOK, VSIZE, DMODEL, 1.f);
}

// round 10
// speedup vs baseline: 2.7446x; 2.7446x over previous
#include <cuda_runtime.h>
#include <math.h>
#include <stdint.h>

// ---------------- problem constants ----------------
#define BATCH   2
#define SEQ     2048
#define NTOK    (BATCH*SEQ)      // 4096
#define DMODEL  512
#define NHEAD   8
#define DHEAD   64
#define NLAYER  4
#define FFDIM   2048
#define SLOTS   32768
#define TOPK    8
#define VSIZE   32000

// ---------------- scratch (device globals; allocation-free rule) ----------------
__device__ float g_x  [NTOK*DMODEL];
__device__ float g_q  [NTOK*DMODEL];
__device__ float g_k  [NTOK*DMODEL];
__device__ float g_v  [NTOK*DMODEL];
__device__ float g_ao [NTOK*DMODEL];
__device__ float g_mq [NTOK*DMODEL];
__device__ float g_rd [NTOK*DMODEL];
__device__ float g_ffh[NTOK*FFDIM];
__device__ float g_big[(long long)NTOK*SLOTS];   // 512MB: attn scores & mem scores (disjoint lifetimes)

// ---------------- helpers ----------------
__device__ __forceinline__ float gelu_tanh(float x) {
    float x3 = x*x*x;
    return 0.5f*x*(1.f + tanhf(0.7978845608028654f*(x + 0.044715f*x3)));
}
__device__ __forceinline__ uint32_t f2tf(float f) {
    uint32_t u; asm("cvt.rna.tf32.f32 %0, %1;" : "=r"(u) : "f"(f)); return u;
}
__device__ __forceinline__ void mma8(float* c, uint32_t a0, uint32_t a1, uint32_t a2, uint32_t a3,
                                     uint32_t b0, uint32_t b1) {
    asm volatile("mma.sync.aligned.m16n8k8.row.col.f32.tf32.tf32.f32 "
                 "{%0,%1,%2,%3},{%4,%5,%6,%7},{%8,%9},{%0,%1,%2,%3};\n"
                 : "+f"(c[0]), "+f"(c[1]), "+f"(c[2]), "+f"(c[3])
                 : "r"(a0), "r"(a1), "r"(a2), "r"(a3), "r"(b0), "r"(b1));
}

// ---------------- tf32 tensor-core GEMM ----------------
// C[r,c] = alpha * sum_k A[r,k]*B(k,c)  (+bias[c]) (+res[r,c]) (opt gelu)
// TB=false: B is [K,N] row-major. TB=true: B is [N,K] row-major, B(k,c)=B[c*ldb+k].
// Batched via blockIdx.z: off = (z/zdiv)*s1 + (z%zdiv)*s2 applied to A,B,C(,res).
// BM=128, BK=32 fixed. 8 warps: 2(m) x 4(n); warp tile 64 x (BN/4).
template<int BN, bool TB, bool GELU>
__global__ __launch_bounds__(256, 1)
void mma_gemm(const float* __restrict__ A, int lda,
              const float* __restrict__ B, int ldb,
              const float* __restrict__ bias,
              const float* __restrict__ res,
              float* __restrict__ C, int ldc,
              int K, float alpha,
              long long sA1, long long sA2,
              long long sB1, long long sB2,
              long long sC1, long long sC2, int zdiv)
{
    constexpr int BM = 128, BK = 32;
    constexpr int WN  = BN/4;           // warp n-extent
    constexpr int NF  = WN/8;           // n fragments per warp (4 or 2)
    constexpr int MF  = 4;              // m fragments per warp (64/16)
    constexpr int ASTR = BK + 4;        // 36: conflict-free frag reads
    constexpr int BTSTR = BK + 4;       // NT layout [n][k]
    constexpr int BNSTR = BN + 8;       // NN layout [k][n]
    constexpr int AP = 4;                                   // float4 per thread (A tile)
    constexpr int BP = TB ? (BN/32) : ((BK*BN)/1024);       // float4 per thread (B tile)
    constexpr int NB4 = BN/4;

    const int z  = blockIdx.z;
    const int z1 = z / zdiv;
    const int z2 = z - z1*zdiv;
    A += z1*sA1 + z2*sA2;
    B += z1*sB1 + z2*sB2;
    const long long coff = z1*sC1 + z2*sC2;
    C += coff;
    const float* resp = res ? (res + coff) : nullptr;

    __shared__ uint32_t As[BM*ASTR];
    __shared__ uint32_t Bs[TB ? (BN*BTSTR) : (BK*BNSTR)];

    const int tid  = threadIdx.x;
    const int warp = tid >> 5;
    const int lane = tid & 31;
    const int wm   = warp & 1;
    const int wn   = warp >> 1;
    const int grp  = lane >> 2;
    const int qid  = lane & 3;

    const long long row0 = (long long)blockIdx.y * BM;
    const long long col0 = (long long)blockIdx.x * BN;

    float acc[MF][NF][4];
#pragma unroll
    for (int mi = 0; mi < MF; mi++)
#pragma unroll
        for (int ni = 0; ni < NF; ni++)
#pragma unroll
            for (int r = 0; r < 4; r++) acc[mi][ni][r] = 0.f;

    const int ntiles = K / BK;
    float4 apref[AP];
    float4 bpref[BP];

    // ---- prefetch tile 0 ----
    {
        const int kc = 4*(tid & 7), ar = tid >> 3;
#pragma unroll
        for (int u = 0; u < AP; u++)
            apref[u] = *(const float4*)(A + (row0 + ar + 32*u)*lda + kc);
        if (TB) {
#pragma unroll
            for (int u = 0; u < BP; u++)
                bpref[u] = *(const float4*)(B + (col0 + ar + 32*u)*(long long)ldb + kc);
        } else {
            const int n4 = 4*(tid % NB4), bk = tid / NB4;
#pragma unroll
            for (int u = 0; u < BP; u++)
                bpref[u] = *(const float4*)(B + (long long)(bk + (256/NB4)*u)*ldb + col0 + n4);
        }
    }

    for (int t = 0; t < ntiles; t++) {
        // ---- store staged tile to smem (tf32-converted) ----
        {
            const int kc = 4*(tid & 7), ar = tid >> 3;
#pragma unroll
            for (int u = 0; u < AP; u++) {
                uint32_t* p = &As[(ar + 32*u)*ASTR + kc];
                p[0] = f2tf(apref[u].x); p[1] = f2tf(apref[u].y);
                p[2] = f2tf(apref[u].z); p[3] = f2tf(apref[u].w);
            }
            if (TB) {
#pragma unroll
                for (int u = 0; u < BP; u++) {
                    uint32_t* p = &Bs[(ar + 32*u)*BTSTR + kc];
                    p[0] = f2tf(bpref[u].x); p[1] = f2tf(bpref[u].y);
                    p[2] = f2tf(bpref[u].z); p[3] = f2tf(bpref[u].w);
                }
            } else {
                const int n4 = 4*(tid % NB4), bk = tid / NB4;
#pragma unroll
                for (int u = 0; u < BP; u++) {
                    uint32_t* p = &Bs[(bk + (256/NB4)*u)*BNSTR + n4];
                    p[0] = f2tf(bpref[u].x); p[1] = f2tf(bpref[u].y);
                    p[2] = f2tf(bpref[u].z); p[3] = f2tf(bpref[u].w);
                }
            }
        }
        __syncthreads();

        // ---- prefetch next tile ----
        if (t + 1 < ntiles) {
            const long long k0 = (long long)(t+1)*BK;
            const int kc = 4*(tid & 7), ar = tid >> 3;
#pragma unroll
            for (int u = 0; u < AP; u++)
                apref[u] = *(const float4*)(A + (row0 + ar + 32*u)*lda + k0 + kc);
            if (TB) {
#pragma unroll
                for (int u = 0; u < BP; u++)
                    bpref[u] = *(const float4*)(B + (col0 + ar + 32*u)*(long long)ldb + k0 + kc);
            } else {
                const int n4 = 4*(tid % NB4), bk = tid / NB4;
#pragma unroll
                for (int u = 0; u < BP; u++)
                    bpref[u] = *(const float4*)(B + (k0 + bk + (256/NB4)*u)*ldb + col0 + n4);
            }
        }

        // ---- compute BK=32 as 4 k-steps of 8 ----
#pragma unroll
        for (int ks = 0; ks < BK/8; ks++) {
            uint32_t af[MF][4], bf[NF][2];
#pragma unroll
            for (int mi = 0; mi < MF; mi++) {
                const uint32_t* ap = &As[(wm*64 + mi*16 + grp)*ASTR + ks*8 + qid];
                af[mi][0] = ap[0];
                af[mi][1] = ap[8*ASTR];
                af[mi][2] = ap[4];
                af[mi][3] = ap[8*ASTR + 4];
            }
#pragma unroll
            for (int ni = 0; ni < NF; ni++) {
                const int nb = wn*WN + ni*8 + grp;
                if (TB) {
                    const uint32_t* bp = &Bs[nb*BTSTR + ks*8 + qid];
                    bf[ni][0] = bp[0];
                    bf[ni][1] = bp[4];
                } else {
                    const uint32_t* bp = &Bs[(ks*8 + qid)*BNSTR + nb];
                    bf[ni][0] = bp[0];
                    bf[ni][1] = bp[4*BNSTR];
                }
            }
#pragma unroll
            for (int mi = 0; mi < MF; mi++)
#pragma unroll
                for (int ni = 0; ni < NF; ni++)
                    mma8(acc[mi][ni], af[mi][0], af[mi][1], af[mi][2], af[mi][3],
                         bf[ni][0], bf[ni][1]);
        }
        __syncthreads();
    }

    // ---- epilogue ----
#pragma unroll
    for (int mi = 0; mi < MF; mi++) {
#pragma unroll
        for (int ni = 0; ni < NF; ni++) {
            const long long rB = row0 + wm*64 + mi*16 + grp;
            const long long cB = col0 + wn*WN + ni*8 + 2*qid;
            float bi0 = 0.f, bi1 = 0.f;
            if (bias) { bi0 = __ldg(bias + cB); bi1 = __ldg(bias + cB + 1); }
#pragma unroll
            for (int h = 0; h < 2; h++) {
                const long long r = rB + 8*h;
                float v0 = acc[mi][ni][2*h]   * alpha + bi0;
                float v1 = acc[mi][ni][2*h+1] * alpha + bi1;
                if (resp) { v0 += resp[r*ldc + cB]; v1 += resp[r*ldc + cB + 1]; }
                if (GELU) { v0 = gelu_tanh(v0); v1 = gelu_tanh(v1); }
                *(float2*)&C[r*ldc + cB] = make_float2(v0, v1);
            }
        }
    }
}

// ---------------- small kernels ----------------
__global__ void embed_kernel(const int* __restrict__ ids,
                             const float* __restrict__ tok,
                             const float* __restrict__ pos,
                             float* __restrict__ x)
{
    int tkn = blockIdx.x;
    int t   = tkn & (SEQ-1);
    int id  = ids[tkn];
    const float* te = tok + (long long)id*DMODEL;
    const float* pe = pos + (long long)t*DMODEL;
    float* xp = x + (long long)tkn*DMODEL;
    for (int d = threadIdx.x; d < DMODEL; d += blockDim.x)
        xp[d] = te[d] + pe[d];
}

// single-pass register-resident softmax over rows of 2048 floats (1R + 1W)
__global__ void softmax_rows_kernel(float* __restrict__ data)
{
    float* p = data + (long long)blockIdx.x * SEQ;
    const int tid  = threadIdx.x;
    const int lane = tid & 31;
    const int warp = tid >> 5;
    __shared__ float red[8];

    float4 a = *(const float4*)(p + 4*tid);          // [0,1024)
    float4 b = *(const float4*)(p + 1024 + 4*tid);   // [1024,2048)

    // ---- row max ----
    float m = fmaxf(fmaxf(fmaxf(a.x, a.y), fmaxf(a.z, a.w)),
                    fmaxf(fmaxf(b.x, b.y), fmaxf(b.z, b.w)));
#pragma unroll
    for (int o = 16; o; o >>= 1) m = fmaxf(m, __shfl_xor_sync(0xffffffffu, m, o));
    if (lane == 0) red[warp] = m;
    __syncthreads();
    float bm = red[0];
#pragma unroll
    for (int i = 1; i < 8; i++) bm = fmaxf(bm, red[i]);
    __syncthreads();   // red[] reused below

    // ---- exp + row sum ----
    a.x = __expf(a.x - bm); a.y = __expf(a.y - bm);
    a.z = __expf(a.z - bm); a.w = __expf(a.w - bm);
    b.x = __expf(b.x - bm); b.y = __expf(b.y - bm);
    b.z = __expf(b.z - bm); b.w = __expf(b.w - bm);
    float s = (a.x + a.y + a.z + a.w) + (b.x + b.y + b.z + b.w);
#pragma unroll
    for (int o = 16; o; o >>= 1) s += __shfl_xor_sync(0xffffffffu, s, o);
    if (lane == 0) red[warp] = s;
    __syncthreads();
    float ts = red[0];
#pragma unroll
    for (int i = 1; i < 8; i++) ts += red[i];
    float inv = 1.f / ts;

    a.x *= inv; a.y *= inv; a.z *= inv; a.w *= inv;
    b.x *= inv; b.y *= inv; b.z *= inv; b.w *= inv;
    *(float4*)(p + 4*tid)        = a;
    *(float4*)(p + 1024 + 4*tid) = b;
}

__global__ void rmsnorm_kernel(float* __restrict__ x, const float* __restrict__ w)
{
    float* p = x + (long long)blockIdx.x * DMODEL;
    const int tid = threadIdx.x;       // 256 threads, 2 elems each
    float a = p[tid], b = p[tid+256];
    __shared__ float red[256];
    red[tid] = a*a + b*b; __syncthreads();
    for (int s = 128; s > 0; s >>= 1) { if (tid < s) red[tid] += red[tid+s]; __syncthreads(); }
    float scale = rsqrtf(red[0]*(1.f/DMODEL) + 1e-8f);
    p[tid]     = a*scale*w[tid];
    p[tid+256] = b*scale*w[tid+256];
}

// per-token: top-8 of 32768 scores -> softmax -> weighted gather of mem_V
__device__ __forceinline__ bool tk_better(float av, int ai, float bv, int bi) {
    return (av > bv) || (av == bv && ai < bi);
}
__global__ void topk_read_kernel(const float* __restrict__ scores,
                                 const float* __restrict__ memV,
                                 float* __restrict__ out)
{
    const int t = blockIdx.x;
    const float* row = scores + (long long)t * SLOTS;
    const int tid = threadIdx.x;

    float v[TOPK]; int ix[TOPK];
#pragma unroll
    for (int i = 0; i < TOPK; i++) { v[i] = -3.4e38f; ix[i] = 1<<30; }

    // vectorized scan: 32768 floats = 8192 float4; 256 threads * 32 each
    const float4* row4 = (const float4*)row;
#pragma unroll 4
    for (int u = 0; u < SLOTS/4/256; u++) {
        int j4 = tid + 256*u;
        float4 s4 = row4[j4];
        float sv4[4] = {s4.x, s4.y, s4.z, s4.w};
#pragma unroll
        for (int c = 0; c < 4; c++) {
            float s = sv4[c];
            int   j = 4*j4 + c;
            if (tk_better(s, j, v[TOPK-1], ix[TOPK-1])) {
                v[TOPK-1] = s; ix[TOPK-1] = j;
#pragma unroll
                for (int p = TOPK-1; p > 0; p--) {
                    if (tk_better(v[p], ix[p], v[p-1], ix[p-1])) {
                        float tv = v[p]; v[p] = v[p-1]; v[p-1] = tv;
                        int   ti = ix[p]; ix[p] = ix[p-1]; ix[p-1] = ti;
                    }
                }
            }
        }
    }

    __shared__ float sv[256][TOPK];
    __shared__ int   si[256][TOPK];
#pragma unroll
    for (int i = 0; i < TOPK; i++) { sv[tid][i] = v[i]; si[tid][i] = ix[i]; }
    __syncthreads();

    for (int s = 128; s > 0; s >>= 1) {
        if (tid < s) {
            float* mv = sv[tid]; int* mi = si[tid];
#pragma unroll
            for (int i = 0; i < TOPK; i++) {
                float cv = sv[tid+s][i]; int ci = si[tid+s][i];
                if (tk_better(cv, ci, mv[TOPK-1], mi[TOPK-1])) {
                    mv[TOPK-1] = cv; mi[TOPK-1] = ci;
#pragma unroll
                    for (int p = TOPK-1; p > 0; p--) {
                        if (tk_better(mv[p], mi[p], mv[p-1], mi[p-1])) {
                            float tv = mv[p]; mv[p] = mv[p-1]; mv[p-1] = tv;
                            int   ti = mi[p]; mi[p] = mi[p-1]; mi[p-1] = ti;
                        }
                    }
                }
            }
        }
        __syncthreads();
    }

    __shared__ float w[TOPK];
    __shared__ int   gidx[TOPK];
    if (tid == 0) {
        float m = sv[0][0];
        float e[TOPK], sum = 0.f;
#pragma unroll
        for (int k2 = 0; k2 < TOPK; k2++) { e[k2] = __expf(sv[0][k2]-m); sum += e[k2]; }
        float inv = 1.f/sum;
#pragma unroll
        for (int k2 = 0; k2 < TOPK; k2++) { w[k2] = e[k2]*inv; gidx[k2] = si[0][k2]; }
    }
    __syncthreads();

    for (int d = tid; d < DMODEL; d += 256) {
        float acc = 0.f;
#pragma unroll
        for (int k2 = 0; k2 < TOPK; k2++)
            acc += w[k2] * memV[(long long)gidx[k2]*DMODEL + d];
        out[(long long)t*DMODEL + d] = acc;
    }
}

// ---------------- host side ----------------
static inline void gemmNN(const float* A, int lda, const float* B, int ldb,
                          const float* bias, const float* res,
                          float* C, int ldc, int M, int N, int K, float alpha)
{
    dim3 g(N/128, M/128, 1), b(256);
    mma_gemm<128,false,false><<<g,b>>>(A,lda,B,ldb,bias,res,C,ldc,K,alpha,0,0,0,0,0,0,1);
}
static inline void gemmNN_gelu(const float* A, int lda, const float* B, int ldb,
                               const float* bias, float* C, int ldc, int M, int N, int K)
{
    dim3 g(N/128, M/128, 1), b(256);
    mma_gemm<128,false,true><<<g,b>>>(A,lda,B,ldb,bias,nullptr,C,ldc,K,1.f,0,0,0,0,0,0,1);
}
static inline void gemmNT(const float* A, int lda, const float* B, int ldb,
                          const float* bias, float* C, int ldc, int M, int N, int K, float alpha)
{
    dim3 g(N/128, M/128, 1), b(256);
    mma_gemm<128,true,false><<<g,b>>>(A,lda,B,ldb,bias,nullptr,C,ldc,K,alpha,0,0,0,0,0,0,1);
}

extern "C" void kernel_launch(void* const* d_in, const int* in_sizes, int n_in,
                              void* d_out, int out_size)
{
    const int*   ids  = (const int*)  d_in[0];
    const float* tok  = (const float*)d_in[1];
    const float* pos  = (const float*)d_in[2];
    const float* wq   = (const float*)d_in[3];
    const float* wk   = (const float*)d_in[4];
    const float* wv   = (const float*)d_in[5];
    const float* wo   = (const float*)d_in[6];
    const float* bo   = (const float*)d_in[7];
    const float* n1   = (const float*)d_in[8];
    const float* fw1  = (const float*)d_in[9];
    const float* fb1  = (const float*)d_in[10];
    const float* fw2  = (const float*)d_in[11];
    const float* fb2  = (const float*)d_in[12];
    const float* n2   = (const float*)d_in[13];
    const float* memK = (const float*)d_in[14];
    const float* memV = (const float*)d_in[15];
    const float* sal  = (const float*)d_in[16];
    const float* wqm  = (const float*)d_in[17];
    const float* bqm  = (const float*)d_in[18];
    const float* wr   = (const float*)d_in[19];
    const float* br   = (const float*)d_in[20];
    const float* now  = (const float*)d_in[21];
    float* out = (float*)d_out;

    float *x,*q,*k,*v,*ao,*mq,*rd,*ffh,*big;
    cudaGetSymbolAddress((void**)&x,   g_x);
    cudaGetSymbolAddress((void**)&q,   g_q);
    cudaGetSymbolAddress((void**)&k,   g_k);
    cudaGetSymbolAddress((void**)&v,   g_v);
    cudaGetSymbolAddress((void**)&ao,  g_ao);
    cudaGetSymbolAddress((void**)&mq,  g_mq);
    cudaGetSymbolAddress((void**)&rd,  g_rd);
    cudaGetSymbolAddress((void**)&ffh, g_ffh);
    cudaGetSymbolAddress((void**)&big, g_big);

    const float inv_sqrt_dh = 0.125f;                 // 64^-0.5
    const float inv_sqrt_d  = 0.044194173824159216f;  // 512^-0.5

    embed_kernel<<<NTOK, 256>>>(ids, tok, pos, x);

    for (int l = 0; l < NLAYER; l++) {
        const float* wql = wq + (long long)l*DMODEL*DMODEL;
        const float* wkl = wk + (long long)l*DMODEL*DMODEL;
        const float* wvl = wv + (long long)l*DMODEL*DMODEL;
        const float* wol = wo + (long long)l*DMODEL*DMODEL;
        const float* bol = bo + (long long)l*DMODEL;
        const float* n1l = n1 + (long long)l*DMODEL;
        const float* f1l = fw1 + (long long)l*DMODEL*FFDIM;
        const float* b1l = fb1 + (long long)l*FFDIM;
        const float* f2l = fw2 + (long long)l*FFDIM*DMODEL;
        const float* b2l = fb2 + (long long)l*DMODEL;
        const float* n2l = n2 + (long long)l*DMODEL;

        gemmNN(x, DMODEL, wql, DMODEL, nullptr, nullptr, q, DMODEL, NTOK, DMODEL, DMODEL, 1.f);
        gemmNN(x, DMODEL, wkl, DMODEL, nullptr, nullptr, k, DMODEL, NTOK, DMODEL, DMODEL, 1.f);
        gemmNN(x, DMODEL, wvl, DMODEL, nullptr, nullptr, v, DMODEL, NTOK, DMODEL, DMODEL, 1.f);

        // scores[b,h,i,j] = 0.125 * q[b,i,h,:] . k[b,j,h,:]   (batched NT, z=(b,h))
        {
            dim3 g(SEQ/128, SEQ/128, BATCH*NHEAD), b(256);
            mma_gemm<128,true,false><<<g,b>>>(
                q, DMODEL, k, DMODEL, nullptr, nullptr, big, SEQ,
                DHEAD, inv_sqrt_dh,
                (long long)SEQ*DMODEL, DHEAD,
                (long long)SEQ*DMODEL, DHEAD,
                (long long)NHEAD*SEQ*SEQ, (long long)SEQ*SEQ,
                NHEAD);
        }
        softmax_rows_kernel<<<BATCH*NHEAD*SEQ, 256>>>(big);
        // ao[b,i,h,:] = attn[b,h,i,:] @ v[b,:,h,:]   (batched NN, N=64)
        {
            dim3 g(1, SEQ/128, BATCH*NHEAD), b(256);
            mma_gemm<64,false,false><<<g,b>>>(
                big, SEQ, v, DMODEL, nullptr, nullptr, ao, DMODEL,
                SEQ, 1.f,
                (long long)NHEAD*SEQ*SEQ, (long long)SEQ*SEQ,
                (long long)SEQ*DMODEL, DHEAD,
                (long long)SEQ*DMODEL, DHEAD,
                NHEAD);
        }

        gemmNN(ao, DMODEL, wol, DMODEL, bol, x, x, DMODEL, NTOK, DMODEL, DMODEL, 1.f);  // x += ao@wo+bo
        rmsnorm_kernel<<<NTOK, 256>>>(x, n1l);
        gemmNN_gelu(x, DMODEL, f1l, FFDIM, b1l, ffh, FFDIM, NTOK, FFDIM, DMODEL);       // h = gelu(x@W1+b1)
        gemmNN(ffh, FFDIM, f2l, DMODEL, b2l, x, x, DMODEL, NTOK, DMODEL, FFDIM, 1.f);   // x += h@W2+b2
        rmsnorm_kernel<<<NTOK, 256>>>(x, n2l);
    }

    // external memory read
    gemmNN(x, DMODEL, wqm, DMODEL, bqm, nullptr, mq, DMODEL, NTOK, DMODEL, DMODEL, 1.f);
    gemmNT(mq, DMODEL, memK, DMODEL, sal, big, SLOTS, NTOK, SLOTS, DMODEL, inv_sqrt_d); // +salience as bias
    topk_read_kernel<<<NTOK, 256>>>(big, memV, rd);
    gemmNN(rd, DMODEL, wr, DMODEL, br, x, x, DMODEL, NTOK, DMODEL, DMODEL, 1.f);        // x += read@w_read+b_read
    rmsnorm_kernel<<<NTOK, 256>>>(x, now);

    // tied LM head: logits = x @ tok^T
    gemmNT(x, DMODEL, tok, DMODEL, nullptr, out, VSIZE, NTOK, VSIZE, DMODEL, 1.f);
}